// round 17
// baseline (speedup 1.0000x reference)
#include <cuda_runtime.h>
#include <cuda_fp16.h>
#include <math.h>
#include <stdint.h>

#define BB   256
#define SS   512
#define DD   512
#define HH   512
#define FCC  64
#define OO   2
#define G4   2048          // 4*H
#define KP   512           // gemm_pre K
#define NKP  16            // KP / 32
#define N5   2560          // 5*H
#define NKT  8             // scan K iters (K=512, 64 per iter)
#define MBLK 8             // m-block groups
#define JBLK 16            // j-blocks per group
#define NTHR 512           // scan threads (16 warps: 2m x 2j x 4k)

// ---- scan smem layout (fp16 element indices) ----
#define PADA     72
#define PADB     40
#define HS_OFF   0
#define CS_OFF   (3 * 32 * PADA)
#define BS_OFF   (2 * 3 * 32 * PADA)
#define STAGE_END (BS_OFF + 3 * 5 * 64 * PADB)          // 52224 elems
#define RED_FOFF  STAGE_END
#define RED_FLOATS (16 * 32 * 32)                        // 16384 floats, stride 32
#define SCAN_SMEM_BYTES (STAGE_END * 2 + RED_FLOATS * 4) // 169984 B

// ---------------------------------------------------------------------------
// Static device scratch (allocation-free contract)
// ---------------------------------------------------------------------------
__device__ __half  g_gx[(size_t)SS * BB * G4];     // fp16 preacts (+bias)
__device__ __half  g_Axhi[(size_t)SS * BB * DD];   // fp16(x)
__device__ __half  g_Wstack[(size_t)KP * G4];      // [512][2048] fp16(W)
__device__ __half  g_Ustack[(size_t)KP * N5];      // [512][2560] fp16(U | Wd)
__device__ float   g_bstack[G4];
__device__ float   g_c[2][BB * HH];
__device__ float   g_h[BB * HH];                   // final h only (head input)
__device__ __half  g_hhi[2][BB * HH];              // fp16(h)
__device__ __half  g_chi[2][BB * HH];              // fp16(c)
__device__ unsigned g_counts[MBLK];                // per-mblock barrier counters

// ---------------------------------------------------------------------------
// PTX helpers
// ---------------------------------------------------------------------------
__device__ __forceinline__ unsigned smem_u32(const void* p)
{
    return (unsigned)__cvta_generic_to_shared(p);
}

#define CP_ASYNC16(dst_u32, src_ptr) \
    asm volatile("cp.async.cg.shared.global [%0],[%1],16;" :: "r"(dst_u32), "l"(src_ptr))
#define CP_COMMIT   asm volatile("cp.async.commit_group;")
#define CP_WAIT1    asm volatile("cp.async.wait_group 1;")
#define CP_WAIT0    asm volatile("cp.async.wait_group 0;")

#define LDSM_X4(r, addr) \
    asm volatile("ldmatrix.sync.aligned.m8n8.x4.shared.b16 {%0,%1,%2,%3},[%4];" \
                 : "=r"((r)[0]), "=r"((r)[1]), "=r"((r)[2]), "=r"((r)[3]) : "r"(addr))
#define LDSM_X4_T(r, addr) \
    asm volatile("ldmatrix.sync.aligned.m8n8.x4.trans.shared.b16 {%0,%1,%2,%3},[%4];" \
                 : "=r"((r)[0]), "=r"((r)[1]), "=r"((r)[2]), "=r"((r)[3]) : "r"(addr))

#define MMA_F16(d, a, b) \
    asm volatile("mma.sync.aligned.m16n8k16.row.col.f32.f16.f16.f32 " \
                 "{%0,%1,%2,%3},{%4,%5,%6,%7},{%8,%9},{%0,%1,%2,%3};" \
                 : "+f"((d)[0]), "+f"((d)[1]), "+f"((d)[2]), "+f"((d)[3]) \
                 : "r"((a)[0]), "r"((a)[1]), "r"((a)[2]), "r"((a)[3]), \
                   "r"((b)[0]), "r"((b)[1]))

__device__ __forceinline__ float sigf(float x) { return 1.0f / (1.0f + expf(-x)); }

__device__ __forceinline__ unsigned ld_acq_u32(const unsigned* p)
{
    unsigned v;
    asm volatile("ld.acquire.gpu.global.b32 %0,[%1];" : "=r"(v) : "l"(p) : "memory");
    return v;
}

// Per-mblock barrier without L1-flushing fences (release/acquire chain).
__device__ __forceinline__ void group_bar(int mb, int t)
{
    __syncthreads();
    if (threadIdx.x == 0) {
        asm volatile("red.release.gpu.global.add.u32 [%0], %1;"
                     :: "l"(&g_counts[mb]), "r"(1u) : "memory");
        const unsigned target = (unsigned)JBLK * (unsigned)(t + 1);
        while (ld_acq_u32(&g_counts[mb]) < target) {
            __nanosleep(32);
        }
    }
    __syncthreads();
}

// ---------------------------------------------------------------------------
// Prep kernels
// ---------------------------------------------------------------------------
__global__ void init_state()
{
    int i = blockIdx.x * blockDim.x + threadIdx.x;
    if (i < MBLK) g_counts[i] = 0u;
    if (i < BB * HH) {
        g_c[0][i] = 0.0f;
        __half z = __float2half_rn(0.0f);
        g_hhi[0][i] = z; g_chi[0][i] = z;
    }
}

__global__ void convert_x(const float* __restrict__ x)
{
    size_t idx = (size_t)blockIdx.x * blockDim.x + threadIdx.x;
    if (idx >= (size_t)SS * BB * DD) return;
    int k = (int)(idx & (DD - 1));
    int m = (int)(idx >> 9);
    int b = m & (BB - 1);
    int t = m >> 8;
    g_Axhi[idx] = __float2half_rn(x[((size_t)b * SS + t) * DD + k]);
}

__global__ void prep_wstack(const float* __restrict__ Wi, const float* __restrict__ Wf,
                            const float* __restrict__ Wog, const float* __restrict__ Wc)
{
    size_t idx = (size_t)blockIdx.x * blockDim.x + threadIdx.x;
    if (idx >= (size_t)KP * G4) return;
    int n = (int)(idx % G4);
    int k = (int)(idx / G4);
    int g = n >> 9;
    int j = n & (HH - 1);
    const float* src = (g == 0) ? Wi : (g == 1) ? Wf : (g == 2) ? Wog : Wc;
    g_Wstack[idx] = __float2half_rn(src[(size_t)k * HH + j]);
}

__global__ void prep_ustack(const float* __restrict__ Ui, const float* __restrict__ Uf,
                            const float* __restrict__ Uog, const float* __restrict__ Uc,
                            const float* __restrict__ Wd)
{
    size_t idx = (size_t)blockIdx.x * blockDim.x + threadIdx.x;
    if (idx >= (size_t)KP * N5) return;
    int n = (int)(idx % N5);
    int k = (int)(idx / N5);
    int g = n >> 9;
    int j = n & (HH - 1);
    const float* src = (g == 0) ? Ui : (g == 1) ? Uf : (g == 2) ? Uog : (g == 3) ? Uc : Wd;
    g_Ustack[idx] = __float2half_rn(src[(size_t)k * HH + j]);
}

__global__ void prep_bias(const float* __restrict__ bi, const float* __restrict__ bf,
                          const float* __restrict__ bog, const float* __restrict__ bc)
{
    int n = blockIdx.x * blockDim.x + threadIdx.x;
    if (n >= G4) return;
    int g = n >> 9, j = n & (HH - 1);
    const float* src = (g == 0) ? bi : (g == 1) ? bf : (g == 2) ? bog : bc;
    g_bstack[n] = src[j];
}

// ---------------------------------------------------------------------------
// Precompute GEMM (unchanged): g_gx(fp16) = x_f16 @ Wstack + b.  K=512.
// ---------------------------------------------------------------------------
__global__ void __launch_bounds__(256, 2) gemm_pre()
{
    __shared__ __half As[2][128][40];
    __shared__ __half Bs[2][32][136];

    const int n0 = blockIdx.x * 128;
    const int m0 = blockIdx.y * 128;
    const int tid = threadIdx.x;
    const int warp = tid >> 5, lane = tid & 31;
    const int wm = warp & 3, wn = warp >> 2;

    const int lrow = (lane & 7) + ((lane >> 3) & 1) * 8;
    const int lcol = (lane >> 4) * 8;

    float acc[2][8][4];
    #pragma unroll
    for (int a = 0; a < 2; a++)
        #pragma unroll
        for (int b = 0; b < 8; b++)
            #pragma unroll
            for (int c = 0; c < 4; c++) acc[a][b][c] = 0.0f;

    auto load_stage = [&](int st, int kk) {
        #pragma unroll
        for (int r = 0; r < 2; r++) {
            int c  = tid + r * 256;
            int arow = c >> 2, ac8 = (c & 3) * 8;
            CP_ASYNC16(smem_u32(&As[st][arow][ac8]),
                       g_Axhi + (size_t)(m0 + arow) * DD + kk + ac8);
            int brow = c >> 4, bc8 = (c & 15) * 8;
            CP_ASYNC16(smem_u32(&Bs[st][brow][bc8]),
                       g_Wstack + (size_t)(kk + brow) * G4 + n0 + bc8);
        }
    };

    load_stage(0, 0);
    CP_COMMIT;

    for (int it = 0; it < NKP; ++it) {
        if (it + 1 < NKP) { load_stage((it + 1) & 1, (it + 1) * 32); CP_COMMIT; CP_WAIT1; }
        else             { CP_WAIT0; }
        __syncthreads();

        const int st = it & 1;
        #pragma unroll
        for (int kh = 0; kh < 2; kh++) {
            const int kb = kh * 16;
            unsigned afr[2][4], bfr[4][4];
            #pragma unroll
            for (int mt = 0; mt < 2; mt++)
                LDSM_X4(afr[mt], smem_u32(&As[st][wm * 32 + mt * 16 + lrow][kb + lcol]));
            #pragma unroll
            for (int nt = 0; nt < 4; nt++)
                LDSM_X4_T(bfr[nt], smem_u32(&Bs[st][kb + lrow][wn * 64 + nt * 16 + lcol]));
            #pragma unroll
            for (int mt = 0; mt < 2; mt++)
                #pragma unroll
                for (int nx = 0; nx < 8; nx++)
                    MMA_F16(acc[mt][nx], afr[mt], &bfr[nx >> 1][(nx & 1) * 2]);
        }
        __syncthreads();
    }

    const int qrow = lane >> 2, qcol = (lane & 3) * 2;
    #pragma unroll
    for (int mt = 0; mt < 2; mt++) {
        #pragma unroll
        for (int rr = 0; rr < 2; rr++) {
            int m = m0 + wm * 32 + mt * 16 + qrow + rr * 8;
            #pragma unroll
            for (int nx = 0; nx < 8; nx++) {
                int n = n0 + wn * 64 + nx * 8 + qcol;
                float2 bv = *(const float2*)&g_bstack[n];
                *(__half2*)&g_gx[(size_t)m * G4 + n] = __halves2half2(
                    __float2half_rn(acc[mt][nx][rr * 2 + 0] + bv.x),
                    __float2half_rn(acc[mt][nx][rr * 2 + 1] + bv.y));
            }
        }
    }
}

// ---------------------------------------------------------------------------
// Persistent TLSTM scan: 512 threads, 4-way split-K (4 warps/SMSP).
// Warps (wm, wj, wk2): each owns k-quarter ko = wk2*16 of every 64-wide iter.
// 4-way accumulator reduction via smem (each warp ships 3 column-slots,
// keeps slot wk2). Barrier-independent W/gx loads pre-issued before group_bar.
// ---------------------------------------------------------------------------
__global__ void __launch_bounds__(NTHR, 1) tlstm_scan(
    const float* __restrict__ timep, const float* __restrict__ bd)
{
    extern __shared__ __half dyn[];
    float* red = (float*)(dyn + RED_FOFF);

    const int mb = blockIdx.x;
    const int m0 = mb * 32;
    const int j0 = blockIdx.y * 32;
    const int tid = threadIdx.x;
    const int warp = tid >> 5, lane = tid & 31;
    const int wm = warp & 1, wj = (warp >> 1) & 1, wk2 = warp >> 2;

    const int lrow = (lane & 7) + ((lane >> 3) & 1) * 8;
    const int lcol = (lane >> 4) * 8;
    const int qrow = lane >> 2, qcol = (lane & 3) * 2;

    // U-weight tiles for stage st, k-chunk itx (t-invariant). 1280 chunks.
    auto load_w = [&](int st, int itx) {
        const int kk = itx * 64;
        #pragma unroll
        for (int q0 = 0; q0 < 3; q0++) {
            int q = tid + q0 * NTHR;
            if (q < 1280) {
                int g = q >> 8;
                int idx = q & 255;
                int row = idx >> 2, c8 = (idx & 3) * 8;
                CP_ASYNC16(smem_u32(&dyn[BS_OFF + ((st * 5 + g) * 64 + row) * PADB + c8]),
                           g_Ustack + (size_t)(kk + row) * N5 + g * HH + j0 + c8);
            }
        }
    };

    auto prefetch_gx = [&](int tt) {
        if (tid < 128) {
            int rr = tid & 31, gg = tid >> 5;
            const __half* p = g_gx + ((size_t)tt * BB + m0 + rr) * G4 + gg * HH + j0;
            asm volatile("prefetch.global.L2 [%0];" :: "l"(p));
        }
    };

    load_w(0, 0);
    load_w(1, 1);
    CP_COMMIT;
    prefetch_gx(0);

    for (int t = 0; t < SS; ++t) {
        const int pp = t & 1;
        const __half* hhi = g_hhi[pp];
        const __half* chi = g_chi[pp];

        // h/c tiles for stage st (barrier-dependent). 512 chunks, 1/thread.
        auto load_hc = [&](int st, int itx) {
            const int kk = itx * 64;
            int tile = tid >> 8;          // 0 = h, 1 = c
            int idx  = tid & 255;
            int row = idx >> 3, c8 = (idx & 7) * 8;
            if (tile == 0)
                CP_ASYNC16(smem_u32(&dyn[HS_OFF + (st * 32 + row) * PADA + c8]),
                           hhi + (size_t)(m0 + row) * HH + kk + c8);
            else
                CP_ASYNC16(smem_u32(&dyn[CS_OFF + (st * 32 + row) * PADA + c8]),
                           chi + (size_t)(m0 + row) * HH + kk + c8);
        };

        load_hc(0, 0);  CP_COMMIT;
        load_hc(1, 1);  CP_COMMIT;

        float accG[4][2][4];
        float accD[2][4];
        #pragma unroll
        for (int g = 0; g < 4; g++)
            #pragma unroll
            for (int n = 0; n < 2; n++)
                #pragma unroll
                for (int c = 0; c < 4; c++) accG[g][n][c] = 0.0f;
        #pragma unroll
        for (int n = 0; n < 2; n++)
            #pragma unroll
            for (int c = 0; c < 4; c++) accD[n][c] = 0.0f;

        const int ko = wk2 * 16;        // this warp's k16 quarter of the 64 iter
        int stC = 0, stL = 2;
        for (int it = 0; it < NKT; ++it) {
            CP_WAIT1;
            __syncthreads();
            if (it + 2 < NKT) { load_w(stL, it + 2); load_hc(stL, it + 2); }
            CP_COMMIT;

            unsigned ah[4], ac[4], bf[5][4];
            LDSM_X4(ah, smem_u32(&dyn[HS_OFF + (stC * 32 + wm * 16 + lrow) * PADA + ko + lcol]));
            LDSM_X4(ac, smem_u32(&dyn[CS_OFF + (stC * 32 + wm * 16 + lrow) * PADA + ko + lcol]));
            #pragma unroll
            for (int g = 0; g < 5; g++)
                LDSM_X4_T(bf[g],
                    smem_u32(&dyn[BS_OFF + ((stC * 5 + g) * 64 + ko + lrow) * PADB + wj * 16 + lcol]));

            #pragma unroll
            for (int g = 0; g < 4; g++) {
                MMA_F16(accG[g][0], ah, &bf[g][0]);
                MMA_F16(accG[g][1], ah, &bf[g][2]);
            }
            MMA_F16(accD[0], ac, &bf[4][0]);
            MMA_F16(accD[1], ac, &bf[4][2]);

            stC = (stC == 2) ? 0 : stC + 1;
            stL = (stL == 2) ? 0 : stL + 1;
        }

        // ---- 4-way cross-warp reduction ----
        // Ship the 3 column-slots this warp doesn't own (slot = acc index c).
        {
            float* myw = &red[(warp * 32 + lane) * 32];
            #pragma unroll
            for (int c = 0; c < 4; c++) {
                if (c != wk2) {
                    int sp = c - (c > wk2 ? 1 : 0);
                    #pragma unroll
                    for (int g = 0; g < 4; g++) {
                        myw[sp * 10 + g * 2 + 0] = accG[g][0][c];
                        myw[sp * 10 + g * 2 + 1] = accG[g][1][c];
                    }
                    myw[sp * 10 + 8] = accD[0][c];
                    myw[sp * 10 + 9] = accD[1][c];
                }
            }
        }
        // Extract owned slot into scalars (compile-time-indexed, predicated).
        float oG[4][2], oD[2];
        #pragma unroll
        for (int c = 0; c < 4; c++) {
            if (c == wk2) {
                #pragma unroll
                for (int g = 0; g < 4; g++) { oG[g][0] = accG[g][0][c]; oG[g][1] = accG[g][1][c]; }
                oD[0] = accD[0][c];  oD[1] = accD[1][c];
            }
        }
        __syncthreads();
        {
            const int base = wm + wj * 2;
            #pragma unroll
            for (int q = 0; q < 4; q++) {
                if (q != wk2) {
                    const float* pr = &red[((base + q * 4) * 32 + lane) * 32];
                    int sp = wk2 - (wk2 > q ? 1 : 0);
                    #pragma unroll
                    for (int g = 0; g < 4; g++) {
                        oG[g][0] += pr[sp * 10 + g * 2 + 0];
                        oG[g][1] += pr[sp * 10 + g * 2 + 1];
                    }
                    oD[0] += pr[sp * 10 + 8];
                    oD[1] += pr[sp * 10 + 9];
                }
            }
        }

        // ------------- elementwise TLSTM update (owned slot) ----------------
        // slot wk2 = (rr_own = wk2>>1, cc_own = wk2&1)
        const int rr_own = wk2 >> 1, cc_own = wk2 & 1;
        const float* c_in  = g_c[pp];
        float*       c_out = g_c[pp ^ 1];
        __half* hhi_o = g_hhi[pp ^ 1];
        __half* chi_o = g_chi[pp ^ 1];

        {
            const int m  = m0 + wm * 16 + rr_own * 8 + qrow;
            const float tv = timep[(size_t)m * SS + t];
            const float Tf = 1.0f / logf(tv + 2.7183f);
            const __half* gxrow = g_gx + ((size_t)t * BB + m) * G4;
            #pragma unroll
            for (int n8 = 0; n8 < 2; n8++) {
                const int j = j0 + wj * 16 + n8 * 8 + qcol + cc_own;
                const float gxi = __half2float(gxrow[0 * HH + j]);
                const float gxf = __half2float(gxrow[1 * HH + j]);
                const float gxo = __half2float(gxrow[2 * HH + j]);
                const float gxc = __half2float(gxrow[3 * HH + j]);
                const float cp  = c_in[(size_t)m * HH + j];
                const float bdv = bd[j];

                float cst = tanhf(oD[n8] + bdv);
                float c1  = cp - cst + Tf * cst;

                float iv = sigf(oG[0][n8] + gxi);
                float fv = sigf(oG[1][n8] + gxf);
                float ov = sigf(oG[2][n8] + gxo);
                float nv = tanhf(oG[3][n8] + gxc);

                float cn = fv * c1 + iv * nv;
                float hn = ov * tanhf(cn);

                size_t off = (size_t)m * HH + j;
                c_out[off] = cn;
                chi_o[off] = __float2half_rn(cn);
                hhi_o[off] = __float2half_rn(hn);
                if (t == SS - 1) g_h[off] = hn;
            }
        }

        // pre-issue barrier-independent loads for step t+1, then barrier.
        if (t + 1 < SS) {
            load_w(0, 0);
            load_w(1, 1);
            CP_COMMIT;
            prefetch_gx(t + 1);
        }

        group_bar(mb, t);
    }
}

// ---------------------------------------------------------------------------
__global__ void head_kernel(const float* __restrict__ Wo, const float* __restrict__ bo,
                            const float* __restrict__ Ws, const float* __restrict__ bs,
                            float* __restrict__ out)
{
    __shared__ float hrow[HH];
    __shared__ float fc[FCC];
    const int b = blockIdx.x;
    const float* h = g_h + (size_t)b * HH;
    for (int k = threadIdx.x; k < HH; k += blockDim.x) hrow[k] = h[k];
    __syncthreads();

    const int j = threadIdx.x;
    float s = bo[j];
    for (int k = 0; k < HH; k++) s += hrow[k] * Wo[(size_t)k * FCC + j];
    fc[j] = fmaxf(s, 0.0f);
    __syncthreads();

    if (j < OO) {
        float r = bs[j];
        for (int q = 0; q < FCC; q++) r += fc[q] * Ws[(size_t)q * OO + j];
        out[(size_t)b * OO + j] = r;
    }
}

// ---------------------------------------------------------------------------
extern "C" void kernel_launch(void* const* d_in, const int* in_sizes, int n_in,
                              void* d_out, int out_size)
{
    const float* x   = (const float*)d_in[0];
    const float* tmv = (const float*)d_in[1];
    const float* Wi  = (const float*)d_in[2];
    const float* Ui  = (const float*)d_in[3];
    const float* bi  = (const float*)d_in[4];
    const float* Wf  = (const float*)d_in[5];
    const float* Uf  = (const float*)d_in[6];
    const float* bf  = (const float*)d_in[7];
    const float* Wog = (const float*)d_in[8];
    const float* Uog = (const float*)d_in[9];
    const float* bog = (const float*)d_in[10];
    const float* Wc  = (const float*)d_in[11];
    const float* Uc  = (const float*)d_in[12];
    const float* bc  = (const float*)d_in[13];
    const float* Wd  = (const float*)d_in[14];
    const float* bd  = (const float*)d_in[15];
    const float* Wo  = (const float*)d_in[16];
    const float* bo  = (const float*)d_in[17];
    const float* Ws  = (const float*)d_in[18];
    const float* bs  = (const float*)d_in[19];
    float* out = (float*)d_out;

    static bool attr_done = false;
    if (!attr_done) {
        cudaFuncSetAttribute(tlstm_scan,
                             cudaFuncAttributeMaxDynamicSharedMemorySize,
                             SCAN_SMEM_BYTES);
        attr_done = true;
    }

    init_state<<<(BB * HH + 255) / 256, 256>>>();

    {   size_t n = (size_t)SS * BB * DD;
        convert_x<<<(unsigned)((n + 255) / 256), 256>>>(x); }
    {   size_t n = (size_t)KP * G4;
        prep_wstack<<<(unsigned)((n + 255) / 256), 256>>>(Wi, Wf, Wog, Wc); }
    {   size_t n = (size_t)KP * N5;
        prep_ustack<<<(unsigned)((n + 255) / 256), 256>>>(Ui, Uf, Uog, Uc, Wd); }
    prep_bias<<<(G4 + 255) / 256, 256>>>(bi, bf, bog, bc);

    dim3 gg(16, 1024);      // x = n-blocks fast -> B L2-resident
    gemm_pre<<<gg, 256>>>();

    dim3 gs(MBLK, JBLK);
    tlstm_scan<<<gs, NTHR, SCAN_SMEM_BYTES>>>(tmv, bd);

    head_kernel<<<BB, FCC>>>(Wo, bo, Ws, bs, out);
}